// round 4
// baseline (speedup 1.0000x reference)
#include <cuda_runtime.h>
#include <math.h>

#define PI_F 3.14159f

// Scratch: __device__ globals (no allocation allowed)
__device__ float g_p[4 * 256];        // relu(pc @ W1 + b1)
__device__ float g_par[4 * 256 * 4];  // per (b,c): m0=scale*cos, m1=scale*sin, tx, ty

// ---------------- MLP stage 1: p = relu(para_code @ W1 + b1) ----------------
__global__ void mlp1_kernel(const float* __restrict__ pc,
                            const float* __restrict__ W1,
                            const float* __restrict__ b1) {
    int b = blockIdx.x;
    int j = threadIdx.x;   // output feature
    __shared__ float s[256];
    s[j] = pc[b * 256 + j];
    __syncthreads();
    float acc = b1[j];
#pragma unroll 8
    for (int i = 0; i < 256; i++)
        acc = fmaf(s[i], W1[i * 256 + j], acc);
    g_p[b * 256 + j] = fmaxf(acc, 0.0f);
}

// ---------------- MLP stage 2: scale/angle/translation -> affine params -----
__global__ void mlp2_kernel(const float* __restrict__ Ws, const float* __restrict__ bs,
                            const float* __restrict__ Wr, const float* __restrict__ br,
                            const float* __restrict__ Wt, const float* __restrict__ bt) {
    int b = blockIdx.x;
    int c = threadIdx.x;   // channel
    __shared__ float s[256];
    s[c] = g_p[b * 256 + c];
    __syncthreads();
    float as = bs[c];
    float ar = br[c];
    float at0 = bt[2 * c];
    float at1 = bt[2 * c + 1];
#pragma unroll 4
    for (int i = 0; i < 256; i++) {
        float pv = s[i];
        as  = fmaf(pv, Ws[i * 256 + c], as);
        ar  = fmaf(pv, Wr[i * 256 + c], ar);
        at0 = fmaf(pv, Wt[i * 512 + 2 * c], at0);
        at1 = fmaf(pv, Wt[i * 512 + 2 * c + 1], at1);
    }
    float scale = 2.0f / (1.0f + expf(-as));    // sigmoid * 2
    float angle = tanhf(ar) * PI_F;
    float ca = cosf(angle), sa = sinf(angle);
    float* o = &g_par[(b * 256 + c) * 4];
    o[0] = scale * ca;
    o[1] = scale * sa;
    o[2] = tanhf(at0);
    o[3] = tanhf(at1);
}

// ---------------- Main sampling kernel --------------------------------------
// One block per (b,c). Stage the two needed z-planes (channels z0,z1) into
// SMEM with padded stride, then each thread bilinear-samples 32 pixels.
static constexpr int PS = 132;                 // padded floats per row (132%32=4 banks, 16B aligned)
static constexpr int PLANE_SM = 128 * PS;      // floats per smem plane

__global__ __launch_bounds__(512, 1)
void sample_kernel(const float* __restrict__ fm, float* __restrict__ out) {
    extern __shared__ float sm[];
    float* s0 = sm;
    float* s1 = sm + PLANE_SM;

    int bc = blockIdx.x;
    int b = bc >> 8;
    int c = bc & 255;
    int tid = threadIdx.x;

    const float* par = &g_par[bc * 4];
    float m0 = par[0], m1 = par[1], tx = par[2], ty = par[3];

    // z coordinate for this channel (depth dim = 256, align_corners=False sampling)
    float zc = 2.0f * ((float)c / 255.0f) - 1.0f;
    float iz = ((zc + 1.0f) * 256.0f - 1.0f) * 0.5f;
    float z0f = floorf(iz);
    float wz = iz - z0f;
    int z0 = (int)z0f;
    int z1 = z0 + 1;
    bool v0 = (z0 >= 0) && (z0 < 256);
    bool v1 = (z1 >= 0) && (z1 < 256);

    const float* base = fm + (size_t)b * (256 * 128 * 128);
    const float4* p0 = (const float4*)(base + (size_t)(v0 ? z0 : 0) * 16384);
    const float4* p1 = (const float4*)(base + (size_t)(v1 ? z1 : 0) * 16384);

    // Load both planes (4096 float4 each) into padded SMEM; invalid plane -> zeros.
#pragma unroll
    for (int it = 0; it < 8; it++) {
        int idx = it * 512 + tid;      // float4 index in plane
        int row = idx >> 5;            // 32 float4 per 128-float row
        int col4 = idx & 31;
        float4 a = v0 ? p0[idx] : make_float4(0.f, 0.f, 0.f, 0.f);
        float4 bqq = v1 ? p1[idx] : make_float4(0.f, 0.f, 0.f, 0.f);
        *(float4*)&s0[row * PS + col4 * 4] = a;
        *(float4*)&s1[row * PS + col4 * 4] = bqq;
    }
    __syncthreads();

    float wza = 1.0f - wz;
    float* op = out + (size_t)bc * 16384;

#pragma unroll 4
    for (int k = 0; k < 32; k++) {
        int pix = k * 512 + tid;
        int h = pix >> 7;
        int w = pix & 127;
        float x = 2.0f * ((float)w / 127.0f) - 1.0f;
        float y = 2.0f * ((float)h / 127.0f) - 1.0f;
        float gx = fmaf(m0, x, fmaf(-m1, y, tx));
        float gy = fmaf(m1, x, fmaf(m0, y, ty));
        float ix = ((gx + 1.0f) * 128.0f - 1.0f) * 0.5f;
        float iy = ((gy + 1.0f) * 128.0f - 1.0f) * 0.5f;
        float x0f = floorf(ix), y0f = floorf(iy);
        float fx = ix - x0f, fy = iy - y0f;
        int x0 = (int)x0f, y0 = (int)y0f;
        int x1i = x0 + 1, y1i = y0 + 1;
        bool vx0 = ((unsigned)x0 < 128u), vx1 = ((unsigned)x1i < 128u);
        bool vy0 = ((unsigned)y0 < 128u), vy1 = ((unsigned)y1i < 128u);
        int cx0 = min(max(x0, 0), 127), cx1 = min(max(x1i, 0), 127);
        int cy0 = min(max(y0, 0), 127), cy1 = min(max(y1i, 0), 127);
        int a00 = cy0 * PS + cx0;
        int a01 = cy0 * PS + cx1;
        int a10 = cy1 * PS + cx0;
        int a11 = cy1 * PS + cx1;
        float w00 = (vy0 && vx0) ? (1.0f - fy) * (1.0f - fx) : 0.0f;
        float w01 = (vy0 && vx1) ? (1.0f - fy) * fx          : 0.0f;
        float w10 = (vy1 && vx0) ? fy * (1.0f - fx)          : 0.0f;
        float w11 = (vy1 && vx1) ? fy * fx                   : 0.0f;
        float q0 = s0[a00] * w00 + s0[a01] * w01 + s0[a10] * w10 + s0[a11] * w11;
        float q1 = s1[a00] * w00 + s1[a01] * w01 + s1[a10] * w10 + s1[a11] * w11;
        op[pix] = fmaf(wza, q0, wz * q1);
    }
}

// ---------------- launch --------------------------------------------------
extern "C" void kernel_launch(void* const* d_in, const int* in_sizes, int n_in,
                              void* d_out, int out_size) {
    const float* feature_map = (const float*)d_in[0];  // [4,256,128,128]
    const float* para_code   = (const float*)d_in[1];  // [4,256]
    const float* W1 = (const float*)d_in[2];
    const float* b1 = (const float*)d_in[3];
    const float* Ws = (const float*)d_in[4];
    const float* bs = (const float*)d_in[5];
    const float* Wr = (const float*)d_in[6];
    const float* br = (const float*)d_in[7];
    const float* Wt = (const float*)d_in[8];
    const float* bt = (const float*)d_in[9];
    float* out = (float*)d_out;

    int smem_bytes = 2 * PLANE_SM * (int)sizeof(float);  // 135168
    cudaFuncSetAttribute(sample_kernel, cudaFuncAttributeMaxDynamicSharedMemorySize,
                         smem_bytes);

    mlp1_kernel<<<4, 256>>>(para_code, W1, b1);
    mlp2_kernel<<<4, 256>>>(Ws, bs, Wr, br, Wt, bt);
    sample_kernel<<<1024, 512, smem_bytes>>>(feature_map, out);
}

// round 7
// speedup vs baseline: 3.0461x; 3.0461x over previous
#include <cuda_runtime.h>
#include <math.h>

#define PI_F 3.14159f

// Scratch: __device__ globals (no allocation allowed)
__device__ float g_p[4 * 256];        // relu(pc @ W1 + b1)
__device__ float g_par[4 * 256 * 4];  // per (b,c): m0=scale*cos, m1=scale*sin, tx, ty

// ---------------- MLP stage 1: p = relu(para_code @ W1 + b1) ----------------
// grid=4 (batch), block=1024: thread = (j = tid&255, q = tid>>8), split-K by 4.
__global__ void mlp1_kernel(const float* __restrict__ pc,
                            const float* __restrict__ W1,
                            const float* __restrict__ b1) {
    int b = blockIdx.x;
    int tid = threadIdx.x;
    int j = tid & 255;
    int q = tid >> 8;           // 0..3
    __shared__ float s[256];
    __shared__ float part[3][256];
    if (tid < 256) s[tid] = pc[b * 256 + tid];
    __syncthreads();
    float acc = 0.0f;
    int i0 = q * 64;
#pragma unroll 16
    for (int i = 0; i < 64; i++)
        acc = fmaf(s[i0 + i], W1[(i0 + i) * 256 + j], acc);
    if (q) part[q - 1][j] = acc;
    __syncthreads();
    if (q == 0) {
        acc += part[0][j] + part[1][j] + part[2][j] + b1[j];
        g_p[b * 256 + j] = fmaxf(acc, 0.0f);
    }
}

// ---------------- MLP stage 2: scale/angle/translation -> affine params -----
// grid=4 (batch), block=1024: thread = (c = tid&255, q = tid>>8), split-K by 4.
__global__ void mlp2_kernel(const float* __restrict__ Ws, const float* __restrict__ bs,
                            const float* __restrict__ Wr, const float* __restrict__ br,
                            const float* __restrict__ Wt, const float* __restrict__ bt) {
    int b = blockIdx.x;
    int tid = threadIdx.x;
    int c = tid & 255;
    int q = tid >> 8;
    __shared__ float s[256];
    __shared__ float4 part[3][256];
    if (tid < 256) s[tid] = g_p[b * 256 + tid];
    __syncthreads();
    float as = 0.0f, ar = 0.0f, at0 = 0.0f, at1 = 0.0f;
    int i0 = q * 64;
#pragma unroll 8
    for (int i = 0; i < 64; i++) {
        float pv = s[i0 + i];
        int row = i0 + i;
        as  = fmaf(pv, Ws[row * 256 + c], as);
        ar  = fmaf(pv, Wr[row * 256 + c], ar);
        at0 = fmaf(pv, Wt[row * 512 + 2 * c], at0);
        at1 = fmaf(pv, Wt[row * 512 + 2 * c + 1], at1);
    }
    if (q) part[q - 1][c] = make_float4(as, ar, at0, at1);
    __syncthreads();
    if (q == 0) {
        float4 p0 = part[0][c], p1 = part[1][c], p2 = part[2][c];
        as  += p0.x + p1.x + p2.x + bs[c];
        ar  += p0.y + p1.y + p2.y + br[c];
        at0 += p0.z + p1.z + p2.z + bt[2 * c];
        at1 += p0.w + p1.w + p2.w + bt[2 * c + 1];
        float scale = 2.0f / (1.0f + expf(-as));    // sigmoid * 2
        float angle = tanhf(ar) * PI_F;
        float ca = cosf(angle), sa = sinf(angle);
        float4 o;
        o.x = scale * ca;
        o.y = scale * sa;
        o.z = tanhf(at0);
        o.w = tanhf(at1);
        *(float4*)&g_par[(b * 256 + c) * 4] = o;
    }
}

// ---------------- Main sampling kernel --------------------------------------
// One block per (b,c). The two needed z-planes are pre-blended (wz is constant
// per block) into ONE SMEM plane with a zero border (rows/cols -1..129).
// Coordinates are clamped in FLOAT space to [-1,128] BEFORE floor, so any
// out-of-range tap lands entirely on zero border cells with correct weights.
static constexpr int PS = 136;                  // padded floats per row
static constexpr int SROWS = 131;               // rows -1 .. 129
static constexpr int PLANE_FLOATS = SROWS * PS; // 17816 (x4 = 71264 B)

__global__ __launch_bounds__(512, 3)
void sample_kernel(const float* __restrict__ fm, float* __restrict__ out) {
    extern __shared__ float sm[];
    int bc = blockIdx.x;
    int b = bc >> 8;
    int c = bc & 255;
    int tid = threadIdx.x;

    // Zero the whole bordered plane (17816 floats = 4454 float4, 16B aligned)
    float4 z4 = make_float4(0.f, 0.f, 0.f, 0.f);
#pragma unroll
    for (int i = tid; i < PLANE_FLOATS / 4; i += 512)
        *(float4*)&sm[i * 4] = z4;

    const float4 par = *(const float4*)&g_par[bc * 4];
    float m0 = par.x, m1 = par.y, tx = par.z, ty = par.w;

    // z coordinate: iz = 128*zc + 127.5, zc = 2*c/255 - 1
    float zc = fmaf(2.0f / 255.0f, (float)c, -1.0f);
    float iz = fmaf(zc, 128.0f, 127.5f);
    float z0f = floorf(iz);
    float wz = iz - z0f;
    float wza = 1.0f - wz;
    int z0 = (int)z0f;
    int z1 = z0 + 1;
    bool v0 = ((unsigned)z0 < 256u);
    bool v1 = ((unsigned)z1 < 256u);

    const float* base = fm + (size_t)b * (256 * 128 * 128);
    const float4* p0 = (const float4*)(base + (size_t)(v0 ? z0 : 0) * 16384);
    const float4* p1 = (const float4*)(base + (size_t)(v1 ? z1 : 0) * 16384);

    __syncthreads();   // zeroing complete

    // Load interior 128x128, blended: s = wza*plane0 + wz*plane1
#pragma unroll
    for (int it = 0; it < 8; it++) {
        int idx = it * 512 + tid;        // float4 index, 32 per row
        int row = idx >> 5;
        int col4 = idx & 31;
        float4 a  = v0 ? p0[idx] : z4;
        float4 bb = v1 ? p1[idx] : z4;
        float4 r;
        r.x = fmaf(wza, a.x, wz * bb.x);
        r.y = fmaf(wza, a.y, wz * bb.y);
        r.z = fmaf(wza, a.z, wz * bb.z);
        r.w = fmaf(wza, a.w, wz * bb.w);
        // interior row r -> smem row r+1; interior col c0 -> smem col c0+4 (16B aligned)
        *(float4*)&sm[(row + 1) * PS + 4 + col4 * 4] = r;
    }
    __syncthreads();

    // Affine directly in index space:
    // ix = 64*gx + 63.5, gx = m0*x - m1*y + tx, x = (2/127)w - 1, y = (2/127)h - 1
    const float s2 = 2.0f / 127.0f;
    float axw = 64.0f * m0 * s2;
    float axh = -64.0f * m1 * s2;
    float cx0 = fmaf(64.0f, tx - m0 + m1, 63.5f);
    float ayw = 64.0f * m1 * s2;
    float ayh = 64.0f * m0 * s2;
    float cy0 = fmaf(64.0f, ty - m1 - m0, 63.5f);

    int w  = tid & 127;          // constant per thread across the loop
    int h0 = tid >> 7;           // 0..3; h steps by 4 each iteration
    float ix = axw * (float)w + axh * (float)h0 + cx0;
    float iy = ayw * (float)w + ayh * (float)h0 + cy0;
    float dix = 4.0f * axh;
    float diy = 4.0f * ayh;

    const float* S = sm + PS + 4;           // (cy,cx) = (0,0)
    float* op = out + (size_t)bc * 16384 + tid;

#pragma unroll 8
    for (int k = 0; k < 32; k++) {
        // Clamp in FLOAT space: out-of-range -> lands on zero border with
        // fractional weight 0 toward the interior. Matches zeros padding.
        float ixc = fminf(fmaxf(ix, -1.0f), 128.0f);
        float iyc = fminf(fmaxf(iy, -1.0f), 128.0f);
        float x0f = floorf(ixc), y0f = floorf(iyc);
        float fx = ixc - x0f, fy = iyc - y0f;
        int cx = (int)x0f;                  // in [-1,128]
        int cy = (int)y0f;
        const float* p = S + cy * PS + cx;
        float v00 = p[0], v01 = p[1];
        float v10 = p[PS], v11 = p[PS + 1];
        float top = fmaf(fx, v01 - v00, v00);
        float bot = fmaf(fx, v11 - v10, v10);
        op[(size_t)k * 512] = fmaf(fy, bot - top, top);
        ix += dix;
        iy += diy;
    }
}

// ---------------- launch --------------------------------------------------
extern "C" void kernel_launch(void* const* d_in, const int* in_sizes, int n_in,
                              void* d_out, int out_size) {
    const float* feature_map = (const float*)d_in[0];  // [4,256,128,128]
    const float* para_code   = (const float*)d_in[1];  // [4,256]
    const float* W1 = (const float*)d_in[2];
    const float* b1 = (const float*)d_in[3];
    const float* Ws = (const float*)d_in[4];
    const float* bs = (const float*)d_in[5];
    const float* Wr = (const float*)d_in[6];
    const float* br = (const float*)d_in[7];
    const float* Wt = (const float*)d_in[8];
    const float* bt = (const float*)d_in[9];
    float* out = (float*)d_out;

    int smem_bytes = PLANE_FLOATS * (int)sizeof(float);  // 71264
    cudaFuncSetAttribute(sample_kernel, cudaFuncAttributeMaxDynamicSharedMemorySize,
                         smem_bytes);

    mlp1_kernel<<<4, 1024>>>(para_code, W1, b1);
    mlp2_kernel<<<4, 1024>>>(Ws, bs, Wr, br, Wt, bt);
    sample_kernel<<<1024, 512, smem_bytes>>>(feature_map, out);
}

// round 8
// speedup vs baseline: 3.1325x; 1.0284x over previous
#include <cuda_runtime.h>
#include <math.h>

#define PI_F 3.14159f

// Scratch: __device__ global (no allocation allowed)
__device__ float g_par[4 * 256 * 4];  // per (b,c): m0=scale*cos, m1=scale*sin, tx, ty

// ---------------- Fused MLP: both stages in one kernel ----------------------
// grid=4 (batch), block=1024: thread = (j/c = tid&255, q = tid>>8), split-K by 4.
__global__ void mlp_kernel(const float* __restrict__ pc,
                           const float* __restrict__ W1, const float* __restrict__ b1,
                           const float* __restrict__ Ws, const float* __restrict__ bs,
                           const float* __restrict__ Wr, const float* __restrict__ br,
                           const float* __restrict__ Wt, const float* __restrict__ bt) {
    int b = blockIdx.x;
    int tid = threadIdx.x;
    int j = tid & 255;          // output feature / channel
    int q = tid >> 8;           // 0..3 k-slice
    __shared__ float s[256];          // input vector
    __shared__ float p[256];          // stage-1 output
    __shared__ float4 part4[3][256];  // split-K partials (stage1 uses .x)

    if (tid < 256) s[tid] = pc[b * 256 + tid];
    __syncthreads();

    // ---- stage 1: p = relu(s @ W1 + b1)
    {
        float acc = 0.0f;
        int i0 = q * 64;
#pragma unroll 16
        for (int i = 0; i < 64; i++)
            acc = fmaf(s[i0 + i], W1[(i0 + i) * 256 + j], acc);
        if (q) part4[q - 1][j].x = acc;
        __syncthreads();
        if (q == 0) {
            acc += part4[0][j].x + part4[1][j].x + part4[2][j].x + b1[j];
            p[j] = fmaxf(acc, 0.0f);
        }
        __syncthreads();
    }

    // ---- stage 2: scale/angle/translation heads
    {
        float as = 0.0f, ar = 0.0f, at0 = 0.0f, at1 = 0.0f;
        int i0 = q * 64;
        int c = j;
#pragma unroll 8
        for (int i = 0; i < 64; i++) {
            float pv = p[i0 + i];
            int row = i0 + i;
            as  = fmaf(pv, Ws[row * 256 + c], as);
            ar  = fmaf(pv, Wr[row * 256 + c], ar);
            at0 = fmaf(pv, Wt[row * 512 + 2 * c], at0);
            at1 = fmaf(pv, Wt[row * 512 + 2 * c + 1], at1);
        }
        if (q) part4[q - 1][c] = make_float4(as, ar, at0, at1);
        __syncthreads();
        if (q == 0) {
            float4 p0 = part4[0][c], p1 = part4[1][c], p2 = part4[2][c];
            as  += p0.x + p1.x + p2.x + bs[c];
            ar  += p0.y + p1.y + p2.y + br[c];
            at0 += p0.z + p1.z + p2.z + bt[2 * c];
            at1 += p0.w + p1.w + p2.w + bt[2 * c + 1];
            float scale = 2.0f / (1.0f + expf(-as));    // sigmoid * 2
            float angle = tanhf(ar) * PI_F;
            float ca = cosf(angle), sa = sinf(angle);
            float4 o;
            o.x = scale * ca;
            o.y = scale * sa;
            o.z = tanhf(at0);
            o.w = tanhf(at1);
            *(float4*)&g_par[(b * 256 + c) * 4] = o;
        }
    }
}

// ---------------- Main sampling kernel --------------------------------------
// One block per (b,c). The two needed z-planes are pre-blended (wz constant
// per block) into ONE SMEM plane with a zero border (rows/cols -1..129).
// Coordinates are clamped in FLOAT space to [-1,128] BEFORE floor, so any
// out-of-range tap lands entirely on zero border cells with correct weights.
// Only the border cells are zeroed (interior is fully overwritten) and the
// zeroing is fused with the load pass -> single __syncthreads.
static constexpr int PS = 136;                  // padded floats per row
static constexpr int SROWS = 131;               // rows -1 .. 129
static constexpr int PLANE_FLOATS = SROWS * PS; // 17816 (x4 = 71264 B)

__global__ __launch_bounds__(512, 3)
void sample_kernel(const float* __restrict__ fm, float* __restrict__ out) {
    extern __shared__ float sm[];
    int bc = blockIdx.x;
    int b = bc >> 8;
    int c = bc & 255;
    int tid = threadIdx.x;

    const float4 par = *(const float4*)&g_par[bc * 4];
    float m0 = par.x, m1 = par.y, tx = par.z, ty = par.w;

    // z coordinate: iz = 128*zc + 127.5, zc = 2*c/255 - 1
    float zc = fmaf(2.0f / 255.0f, (float)c, -1.0f);
    float iz = fmaf(zc, 128.0f, 127.5f);
    float z0f = floorf(iz);
    float wz = iz - z0f;
    float wza = 1.0f - wz;
    int z0 = (int)z0f;
    int z1 = z0 + 1;
    bool v0 = ((unsigned)z0 < 256u);
    bool v1 = ((unsigned)z1 < 256u);

    const float* base = fm + (size_t)b * (256 * 128 * 128);
    const float4* p0 = (const float4*)(base + (size_t)(v0 ? z0 : 0) * 16384);
    const float4* p1 = (const float4*)(base + (size_t)(v1 ? z1 : 0) * 16384);

    float4 z4 = make_float4(0.f, 0.f, 0.f, 0.f);

    // Zero ONLY the border cells: rows {0,129,130} full (3*34 float4) plus
    // side columns (col4 0 and 33) for rows 1..128 (256 float4). 358 total.
    if (tid < 358) {
        int row, col4;
        if (tid < 102) {
            int r = tid / 34;                 // 0..2
            row = (r == 0) ? 0 : (128 + r);   // 0,129,130
            col4 = tid - r * 34;              // 0..33
        } else {
            int t = tid - 102;
            row = 1 + (t >> 1);               // 1..128
            col4 = (t & 1) ? 33 : 0;
        }
        *(float4*)&sm[row * PS + col4 * 4] = z4;
    }

    // Load interior 128x128, blended: s = wza*plane0 + wz*plane1.
    // Interior row r -> smem row r+1; interior col c0 -> smem col c0+4.
#pragma unroll
    for (int it = 0; it < 8; it++) {
        int idx = it * 512 + tid;        // float4 index, 32 per row
        int row = idx >> 5;
        int col4 = idx & 31;
        float4 a  = v0 ? p0[idx] : z4;
        float4 bb = v1 ? p1[idx] : z4;
        float4 r;
        r.x = fmaf(wza, a.x, wz * bb.x);
        r.y = fmaf(wza, a.y, wz * bb.y);
        r.z = fmaf(wza, a.z, wz * bb.z);
        r.w = fmaf(wza, a.w, wz * bb.w);
        *(float4*)&sm[(row + 1) * PS + 4 + col4 * 4] = r;
    }
    __syncthreads();   // single barrier: border zeros + blended interior ready

    // Affine directly in index space:
    // ix = 64*gx + 63.5, gx = m0*x - m1*y + tx, x = (2/127)w - 1, y = (2/127)h - 1
    const float s2 = 2.0f / 127.0f;
    float axw = 64.0f * m0 * s2;
    float axh = -64.0f * m1 * s2;
    float cx0 = fmaf(64.0f, tx - m0 + m1, 63.5f);
    float ayw = 64.0f * m1 * s2;
    float ayh = 64.0f * m0 * s2;
    float cy0 = fmaf(64.0f, ty - m1 - m0, 63.5f);

    int w  = tid & 127;          // constant per thread across the loop
    int h0 = tid >> 7;           // 0..3; h steps by 4 each iteration
    float ix = axw * (float)w + axh * (float)h0 + cx0;
    float iy = ayw * (float)w + ayh * (float)h0 + cy0;
    float dix = 4.0f * axh;
    float diy = 4.0f * ayh;

    const float* S = sm + PS + 4;           // (cy,cx) = (0,0)
    float* op = out + (size_t)bc * 16384 + tid;

#pragma unroll 8
    for (int k = 0; k < 32; k++) {
        // Clamp in FLOAT space: out-of-range lands on zero border with
        // fractional weight 0 toward the interior. Matches zeros padding.
        float ixc = fminf(fmaxf(ix, -1.0f), 128.0f);
        float iyc = fminf(fmaxf(iy, -1.0f), 128.0f);
        int cx = __float2int_rd(ixc);       // in [-1,128], single cvt.rmi
        int cy = __float2int_rd(iyc);
        float fx = ixc - (float)cx;
        float fy = iyc - (float)cy;
        const float* p = S + cy * PS + cx;
        float v00 = p[0], v01 = p[1];
        float v10 = p[PS], v11 = p[PS + 1];
        float top = fmaf(fx, v01 - v00, v00);
        float bot = fmaf(fx, v11 - v10, v10);
        op[(size_t)k * 512] = fmaf(fy, bot - top, top);
        ix += dix;
        iy += diy;
    }
}

// ---------------- launch --------------------------------------------------
extern "C" void kernel_launch(void* const* d_in, const int* in_sizes, int n_in,
                              void* d_out, int out_size) {
    const float* feature_map = (const float*)d_in[0];  // [4,256,128,128]
    const float* para_code   = (const float*)d_in[1];  // [4,256]
    const float* W1 = (const float*)d_in[2];
    const float* b1 = (const float*)d_in[3];
    const float* Ws = (const float*)d_in[4];
    const float* bs = (const float*)d_in[5];
    const float* Wr = (const float*)d_in[6];
    const float* br = (const float*)d_in[7];
    const float* Wt = (const float*)d_in[8];
    const float* bt = (const float*)d_in[9];
    float* out = (float*)d_out;

    int smem_bytes = PLANE_FLOATS * (int)sizeof(float);  // 71264
    cudaFuncSetAttribute(sample_kernel, cudaFuncAttributeMaxDynamicSharedMemorySize,
                         smem_bytes);

    mlp_kernel<<<4, 1024>>>(para_code, W1, b1, Ws, bs, Wr, br, Wt, bt);
    sample_kernel<<<1024, 512, smem_bytes>>>(feature_map, out);
}

// round 9
// speedup vs baseline: 3.9087x; 1.2478x over previous
#include <cuda_runtime.h>
#include <math.h>

#define PI_F 3.14159f

// Scratch: __device__ global (no allocation allowed)
__device__ float g_p[4 * 256];   // relu(pc @ W1 + b1)

// ---------------- MLP stage 1 (wide): p = relu(pc @ W1 + b1) ----------------
// grid = 64 (b*16 + jg), block = 256: jl = tid&15 (output within group),
// q = tid>>4 (k-slice of 16). Coalesced 64B W1 loads per warp.
__global__ void mlp1_kernel(const float* __restrict__ pc,
                            const float* __restrict__ W1,
                            const float* __restrict__ b1) {
    int blk = blockIdx.x;
    int b = blk >> 4;
    int jg = blk & 15;
    int tid = threadIdx.x;
    int jl = tid & 15;
    int q = tid >> 4;
    int j = jg * 16 + jl;
    __shared__ float s[256];
    __shared__ float part[256];      // [q*16 + jl]
    s[tid] = pc[b * 256 + tid];
    __syncthreads();
    float acc = 0.0f;
    int k0 = q * 16;
#pragma unroll
    for (int i = 0; i < 16; i++)
        acc = fmaf(s[k0 + i], W1[(k0 + i) * 256 + j], acc);
    part[tid] = acc;
    __syncthreads();
    if (tid < 16) {                  // tid == jl
        float a = b1[jg * 16 + tid];
#pragma unroll
        for (int qq = 0; qq < 16; qq++) a += part[qq * 16 + tid];
        g_p[b * 256 + jg * 16 + tid] = fmaxf(a, 0.0f);
    }
}

// ---------------- Main sampling kernel (mlp2 fused in) ----------------------
// One block per (b,c). Plane pair pre-blended (wz constant per block) into ONE
// SMEM plane with zero border (rows/cols -1..129). The per-(b,c) affine params
// (scale*rot, translation) are computed IN-BLOCK from g_p and the head weight
// columns, hidden behind the plane LDGs.
static constexpr int PS = 136;                  // padded floats per row
static constexpr int SROWS = 131;               // rows -1 .. 129
static constexpr int PLANE_FLOATS = SROWS * PS; // 17816
static constexpr int SM_EXTRA = 32;             // 16 reduce slots + 4 raw + pad
static constexpr int SM_TOTAL = PLANE_FLOATS + SM_EXTRA;

__global__ __launch_bounds__(512, 3)
void sample_kernel(const float* __restrict__ fm, float* __restrict__ out,
                   const float* __restrict__ Ws, const float* __restrict__ bs,
                   const float* __restrict__ Wr, const float* __restrict__ br,
                   const float* __restrict__ Wt, const float* __restrict__ bt) {
    extern __shared__ float sm[];
    float* red = sm + PLANE_FLOATS;   // [16] per-warp partials
    float* raw = red + 16;            // [4] raw head sums (pre-activation)

    int bc = blockIdx.x;
    int b = bc >> 8;
    int c = bc & 255;
    int tid = threadIdx.x;

    // z coordinate: iz = 128*zc + 127.5, zc = 2*c/255 - 1
    float zc = fmaf(2.0f / 255.0f, (float)c, -1.0f);
    float iz = fmaf(zc, 128.0f, 127.5f);
    float z0f = floorf(iz);
    float wz = iz - z0f;
    float wza = 1.0f - wz;
    int z0 = (int)z0f;
    int z1 = z0 + 1;
    bool v0 = ((unsigned)z0 < 256u);
    bool v1 = ((unsigned)z1 < 256u);

    const float* base = fm + (size_t)b * (256 * 128 * 128);
    const float4* p0 = (const float4*)(base + (size_t)(v0 ? z0 : 0) * 16384);
    const float4* p1 = (const float4*)(base + (size_t)(v1 ? z1 : 0) * 16384);

    float4 z4 = make_float4(0.f, 0.f, 0.f, 0.f);

    // Zero ONLY the border cells: rows {0,129,130} full (3*34 float4) plus
    // side columns (col4 0 and 33) for rows 1..128 (256 float4). 358 total.
    if (tid < 358) {
        int row, col4;
        if (tid < 102) {
            int r = tid / 34;                 // 0..2
            row = (r == 0) ? 0 : (128 + r);   // 0,129,130
            col4 = tid - r * 34;              // 0..33
        } else {
            int t = tid - 102;
            row = 1 + (t >> 1);               // 1..128
            col4 = (t & 1) ? 33 : 0;
        }
        *(float4*)&sm[row * PS + col4 * 4] = z4;
    }

    // Load interior 128x128, blended: s = wza*plane0 + wz*plane1.
#pragma unroll
    for (int it = 0; it < 8; it++) {
        int idx = it * 512 + tid;        // float4 index, 32 per row
        int row = idx >> 5;
        int col4 = idx & 31;
        float4 a  = v0 ? p0[idx] : z4;
        float4 bb = v1 ? p1[idx] : z4;
        float4 r;
        r.x = fmaf(wza, a.x, wz * bb.x);
        r.y = fmaf(wza, a.y, wz * bb.y);
        r.z = fmaf(wza, a.z, wz * bb.z);
        r.w = fmaf(wza, a.w, wz * bb.w);
        *(float4*)&sm[(row + 1) * PS + 4 + col4 * 4] = r;
    }

    // ---- fused mlp2: 4 heads (s, r, t0, t1), 128 threads per head,
    // 2 rows per thread. LDGs overlap the plane LDGs above.
    {
        int r = tid & 127;
        int h = tid >> 7;                 // 0..3
        const float* pv = g_p + b * 256;
        const float* Wc;
        int stride;
        if (h == 0)      { Wc = Ws + c;         stride = 256; }
        else if (h == 1) { Wc = Wr + c;         stride = 256; }
        else if (h == 2) { Wc = Wt + 2 * c;     stride = 512; }
        else             { Wc = Wt + 2 * c + 1; stride = 512; }
        float acc = pv[r] * Wc[(size_t)r * stride]
                  + pv[r + 128] * Wc[(size_t)(r + 128) * stride];
#pragma unroll
        for (int off = 16; off; off >>= 1)
            acc += __shfl_down_sync(0xFFFFFFFFu, acc, off);
        if ((tid & 31) == 0) red[tid >> 5] = acc;   // warp id 0..15
    }
    __syncthreads();   // plane STS + border zeros + warp partials ready

    if (tid < 4) {
        float a = red[tid * 4] + red[tid * 4 + 1] + red[tid * 4 + 2] + red[tid * 4 + 3];
        float bias = (tid == 0) ? bs[c] : (tid == 1) ? br[c]
                   : (tid == 2) ? bt[2 * c] : bt[2 * c + 1];
        raw[tid] = a + bias;
    }
    __syncthreads();

    // All threads compute activations redundantly (cheap, avoids 3rd barrier)
    float scale = 2.0f / (1.0f + expf(-raw[0]));
    float angle = tanhf(raw[1]) * PI_F;
    float m0 = scale * cosf(angle);
    float m1 = scale * sinf(angle);
    float tx = tanhf(raw[2]);
    float ty = tanhf(raw[3]);

    // Affine in index space:
    // ix = 64*gx + 63.5, gx = m0*x - m1*y + tx, x = (2/127)w - 1, y = (2/127)h - 1
    const float s2 = 2.0f / 127.0f;
    float axw = 64.0f * m0 * s2;
    float axh = -64.0f * m1 * s2;
    float cx0 = fmaf(64.0f, tx - m0 + m1, 63.5f);
    float ayw = 64.0f * m1 * s2;
    float ayh = 64.0f * m0 * s2;
    float cy0 = fmaf(64.0f, ty - m1 - m0, 63.5f);

    int w  = tid & 127;          // constant per thread across the loop
    int h0 = tid >> 7;           // 0..3; h steps by 4 each iteration
    float ix = axw * (float)w + axh * (float)h0 + cx0;
    float iy = ayw * (float)w + ayh * (float)h0 + cy0;
    float dix = 4.0f * axh;
    float diy = 4.0f * ayh;

    const float* S = sm + PS + 4;           // (cy,cx) = (0,0)
    float* op = out + (size_t)bc * 16384 + tid;

#pragma unroll 8
    for (int k = 0; k < 32; k++) {
        // Clamp in FLOAT space BEFORE floor: out-of-range taps land entirely
        // on zero border cells with correct weights (matches zeros padding).
        float ixc = fminf(fmaxf(ix, -1.0f), 128.0f);
        float iyc = fminf(fmaxf(iy, -1.0f), 128.0f);
        int cx = __float2int_rd(ixc);       // in [-1,128]
        int cy = __float2int_rd(iyc);
        float fx = ixc - (float)cx;
        float fy = iyc - (float)cy;
        const float* p = S + cy * PS + cx;
        float v00 = p[0], v01 = p[1];
        float v10 = p[PS], v11 = p[PS + 1];
        float top = fmaf(fx, v01 - v00, v00);
        float bot = fmaf(fx, v11 - v10, v10);
        op[(size_t)k * 512] = fmaf(fy, bot - top, top);
        ix += dix;
        iy += diy;
    }
}

// ---------------- launch --------------------------------------------------
extern "C" void kernel_launch(void* const* d_in, const int* in_sizes, int n_in,
                              void* d_out, int out_size) {
    const float* feature_map = (const float*)d_in[0];  // [4,256,128,128]
    const float* para_code   = (const float*)d_in[1];  // [4,256]
    const float* W1 = (const float*)d_in[2];
    const float* b1 = (const float*)d_in[3];
    const float* Ws = (const float*)d_in[4];
    const float* bs = (const float*)d_in[5];
    const float* Wr = (const float*)d_in[6];
    const float* br = (const float*)d_in[7];
    const float* Wt = (const float*)d_in[8];
    const float* bt = (const float*)d_in[9];
    float* out = (float*)d_out;

    int smem_bytes = SM_TOTAL * (int)sizeof(float);   // 71392
    cudaFuncSetAttribute(sample_kernel, cudaFuncAttributeMaxDynamicSharedMemorySize,
                         smem_bytes);

    mlp1_kernel<<<64, 256>>>(para_code, W1, b1);
    sample_kernel<<<1024, 512, smem_bytes>>>(feature_map, out,
                                             Ws, bs, Wr, br, Wt, bt);
}

// round 10
// speedup vs baseline: 3.9305x; 1.0056x over previous
#include <cuda_runtime.h>
#include <math.h>

#define PI_F 3.14159f

// Scratch: __device__ globals (no allocation allowed)
__device__ float g_p[4 * 256];        // relu(pc @ W1 + b1)
__device__ float g_par[4 * 256 * 4];  // per (b,c): m0=scale*cos, m1=scale*sin, tx, ty

// ---------------- MLP stage 1 (wide): p = relu(pc @ W1 + b1) ----------------
// grid = 64 (b*16 + jg), block = 256: jl = tid&15 (output within group),
// q = tid>>4 (k-slice of 16). Coalesced 64B W1 loads per half-warp.
__global__ void mlp1_kernel(const float* __restrict__ pc,
                            const float* __restrict__ W1,
                            const float* __restrict__ b1) {
    int blk = blockIdx.x;
    int b = blk >> 4;
    int jg = blk & 15;
    int tid = threadIdx.x;
    int jl = tid & 15;
    int q = tid >> 4;
    int j = jg * 16 + jl;
    __shared__ float s[256];
    __shared__ float part[256];      // [q*16 + jl]
    s[tid] = pc[b * 256 + tid];
    __syncthreads();
    float acc = 0.0f;
    int k0 = q * 16;
#pragma unroll
    for (int i = 0; i < 16; i++)
        acc = fmaf(s[k0 + i], W1[(k0 + i) * 256 + j], acc);
    part[tid] = acc;
    __syncthreads();
    if (tid < 16) {                  // tid == jl
        float a = b1[jg * 16 + tid];
#pragma unroll
        for (int qq = 0; qq < 16; qq++) a += part[qq * 16 + tid];
        g_p[b * 256 + jg * 16 + tid] = fmaxf(a, 0.0f);
    }
}

// ---------------- MLP stage 2 (wide): heads -> g_par ------------------------
// grid = 64 (b*16 + cg), block = 256: cl = tid&15 (channel in group),
// q = tid>>4 (k-slice of 16). c-major lanes -> coalesced weight loads.
__global__ void mlp2_kernel(const float* __restrict__ Ws, const float* __restrict__ bs,
                            const float* __restrict__ Wr, const float* __restrict__ br,
                            const float* __restrict__ Wt, const float* __restrict__ bt) {
    int blk = blockIdx.x;
    int b = blk >> 4;
    int cg = blk & 15;
    int tid = threadIdx.x;
    int cl = tid & 15;
    int q = tid >> 4;
    int c = cg * 16 + cl;
    __shared__ float s[256];
    __shared__ float4 part[256];     // [q*16 + cl]
    s[tid] = g_p[b * 256 + tid];
    __syncthreads();
    float as = 0.0f, ar = 0.0f, at0 = 0.0f, at1 = 0.0f;
    int k0 = q * 16;
#pragma unroll
    for (int i = 0; i < 16; i++) {
        int row = k0 + i;
        float pv = s[row];
        as  = fmaf(pv, Ws[row * 256 + c], as);
        ar  = fmaf(pv, Wr[row * 256 + c], ar);
        at0 = fmaf(pv, Wt[row * 512 + 2 * c], at0);
        at1 = fmaf(pv, Wt[row * 512 + 2 * c + 1], at1);
    }
    part[tid] = make_float4(as, ar, at0, at1);
    __syncthreads();
    if (tid < 16) {                  // tid == cl
        int cc = cg * 16 + tid;
        float a0 = bs[cc], a1 = br[cc], a2 = bt[2 * cc], a3 = bt[2 * cc + 1];
#pragma unroll
        for (int qq = 0; qq < 16; qq++) {
            float4 v = part[qq * 16 + tid];
            a0 += v.x; a1 += v.y; a2 += v.z; a3 += v.w;
        }
        float scale = 2.0f / (1.0f + expf(-a0));    // sigmoid * 2
        float angle = tanhf(a1) * PI_F;
        float ca = cosf(angle), sa = sinf(angle);
        float4 o;
        o.x = scale * ca;
        o.y = scale * sa;
        o.z = tanhf(a2);
        o.w = tanhf(a3);
        *(float4*)&g_par[(b * 256 + cc) * 4] = o;
    }
}

// ---------------- Main sampling kernel --------------------------------------
// One block per (b,c). The two needed z-planes are pre-blended (wz constant
// per block) into ONE SMEM plane with a zero border (rows/cols -1..129).
// Coordinates are clamped in FLOAT space to [-1,128] BEFORE floor, so any
// out-of-range tap lands entirely on zero border cells with correct weights.
// Only the border cells are zeroed; zeroing fused with load pass -> 1 barrier.
static constexpr int PS = 136;                  // padded floats per row
static constexpr int SROWS = 131;               // rows -1 .. 129
static constexpr int PLANE_FLOATS = SROWS * PS; // 17816 (x4 = 71264 B)

__global__ __launch_bounds__(512, 3)
void sample_kernel(const float* __restrict__ fm, float* __restrict__ out) {
    extern __shared__ float sm[];
    int bc = blockIdx.x;
    int b = bc >> 8;
    int c = bc & 255;
    int tid = threadIdx.x;

    const float4 par = *(const float4*)&g_par[bc * 4];
    float m0 = par.x, m1 = par.y, tx = par.z, ty = par.w;

    // z coordinate: iz = 128*zc + 127.5, zc = 2*c/255 - 1
    float zc = fmaf(2.0f / 255.0f, (float)c, -1.0f);
    float iz = fmaf(zc, 128.0f, 127.5f);
    float z0f = floorf(iz);
    float wz = iz - z0f;
    float wza = 1.0f - wz;
    int z0 = (int)z0f;
    int z1 = z0 + 1;
    bool v0 = ((unsigned)z0 < 256u);
    bool v1 = ((unsigned)z1 < 256u);

    const float* base = fm + (size_t)b * (256 * 128 * 128);
    const float4* p0 = (const float4*)(base + (size_t)(v0 ? z0 : 0) * 16384);
    const float4* p1 = (const float4*)(base + (size_t)(v1 ? z1 : 0) * 16384);

    float4 z4 = make_float4(0.f, 0.f, 0.f, 0.f);

    // Zero ONLY the border cells: rows {0,129,130} full (3*34 float4) plus
    // side columns (col4 0 and 33) for rows 1..128 (256 float4). 358 total.
    if (tid < 358) {
        int row, col4;
        if (tid < 102) {
            int r = tid / 34;                 // 0..2
            row = (r == 0) ? 0 : (128 + r);   // 0,129,130
            col4 = tid - r * 34;              // 0..33
        } else {
            int t = tid - 102;
            row = 1 + (t >> 1);               // 1..128
            col4 = (t & 1) ? 33 : 0;
        }
        *(float4*)&sm[row * PS + col4 * 4] = z4;
    }

    // Load interior 128x128, blended: s = wza*plane0 + wz*plane1.
    // Interior row r -> smem row r+1; interior col c0 -> smem col c0+4.
#pragma unroll
    for (int it = 0; it < 8; it++) {
        int idx = it * 512 + tid;        // float4 index, 32 per row
        int row = idx >> 5;
        int col4 = idx & 31;
        float4 a  = v0 ? p0[idx] : z4;
        float4 bb = v1 ? p1[idx] : z4;
        float4 r;
        r.x = fmaf(wza, a.x, wz * bb.x);
        r.y = fmaf(wza, a.y, wz * bb.y);
        r.z = fmaf(wza, a.z, wz * bb.z);
        r.w = fmaf(wza, a.w, wz * bb.w);
        *(float4*)&sm[(row + 1) * PS + 4 + col4 * 4] = r;
    }
    __syncthreads();   // single barrier: border zeros + blended interior ready

    // Affine in index space:
    // ix = 64*gx + 63.5, gx = m0*x - m1*y + tx, x = (2/127)w - 1, y = (2/127)h - 1
    const float s2 = 2.0f / 127.0f;
    float axw = 64.0f * m0 * s2;
    float axh = -64.0f * m1 * s2;
    float cx0 = fmaf(64.0f, tx - m0 + m1, 63.5f);
    float ayw = 64.0f * m1 * s2;
    float ayh = 64.0f * m0 * s2;
    float cy0 = fmaf(64.0f, ty - m1 - m0, 63.5f);

    int w  = tid & 127;          // constant per thread across the loop
    int h0 = tid >> 7;           // 0..3; h steps by 4 each iteration
    float ix = axw * (float)w + axh * (float)h0 + cx0;
    float iy = ayw * (float)w + ayh * (float)h0 + cy0;
    float dix = 4.0f * axh;
    float diy = 4.0f * ayh;

    const float* S = sm + PS + 4;           // (cy,cx) = (0,0)
    float* op = out + (size_t)bc * 16384 + tid;

#pragma unroll 8
    for (int k = 0; k < 32; k++) {
        // Clamp in FLOAT space BEFORE floor: out-of-range taps land entirely
        // on zero border cells with correct weights (matches zeros padding).
        float ixc = fminf(fmaxf(ix, -1.0f), 128.0f);
        float iyc = fminf(fmaxf(iy, -1.0f), 128.0f);
        int cx = __float2int_rd(ixc);       // in [-1,128]
        int cy = __float2int_rd(iyc);
        float fx = ixc - (float)cx;
        float fy = iyc - (float)cy;
        const float* p = S + cy * PS + cx;
        float v00 = p[0], v01 = p[1];
        float v10 = p[PS], v11 = p[PS + 1];
        float top = fmaf(fx, v01 - v00, v00);
        float bot = fmaf(fx, v11 - v10, v10);
        op[(size_t)k * 512] = fmaf(fy, bot - top, top);
        ix += dix;
        iy += diy;
    }
}

// ---------------- launch --------------------------------------------------
extern "C" void kernel_launch(void* const* d_in, const int* in_sizes, int n_in,
                              void* d_out, int out_size) {
    const float* feature_map = (const float*)d_in[0];  // [4,256,128,128]
    const float* para_code   = (const float*)d_in[1];  // [4,256]
    const float* W1 = (const float*)d_in[2];
    const float* b1 = (const float*)d_in[3];
    const float* Ws = (const float*)d_in[4];
    const float* bs = (const float*)d_in[5];
    const float* Wr = (const float*)d_in[6];
    const float* br = (const float*)d_in[7];
    const float* Wt = (const float*)d_in[8];
    const float* bt = (const float*)d_in[9];
    float* out = (float*)d_out;

    int smem_bytes = PLANE_FLOATS * (int)sizeof(float);  // 71264
    cudaFuncSetAttribute(sample_kernel, cudaFuncAttributeMaxDynamicSharedMemorySize,
                         smem_bytes);

    mlp1_kernel<<<64, 256>>>(para_code, W1, b1);
    mlp2_kernel<<<64, 256>>>(Ws, bs, Wr, br, Wt, bt);
    sample_kernel<<<1024, 512, smem_bytes>>>(feature_map, out);
}